// round 2
// baseline (speedup 1.0000x reference)
#include <cuda_runtime.h>

// FlowNetC correlation on GB300 — round 2.
// out[b, dy*21+dx, y, x] = (1/256) * sum_c in1[b,c,y,x] * in2[b,c, y+2dy-20, x+2dx-20]
//
// Block = (dy-group of 7, y, b). 7 warps, one warp per dy.
// Parity de-interleaved smem; thread owns 4 same-parity x * 21 dx = 84 accs.
// R2 changes: CK=8 -> CK=4 (prefetch regs 32->16), hoisted incrementing global
// pointers + precomputed smem store offsets, __launch_bounds__(224, 2) for
// 2 blocks/SM (14 warps) to fix the 11% occupancy / 43.8% issue bottleneck.

#define NW        7
#define CK        4          // channels per smem chunk
#define NTHREADS  (NW * 32)  // 224
#define C_TOT     256
#define NCHUNK    (C_TOT / CK)   // 64
#define H         96
#define W         128
#define DD        21

struct __align__(16) Smem {
    float in2s[NW][CK][2][84];   // [dy][c][parity][pad10 | 64 | pad10]  18816 B
    float in1s[CK][2][64];       //                                       2048 B
    float stage[NW][128];        // output transpose staging              3584 B
};                               // 24448 B -> 2 blocks/SM = 48.9 KB

__global__ void __launch_bounds__(NTHREADS, 2) corr_kernel(
    const float* __restrict__ g_in1,
    const float* __restrict__ g_in2,
    float*       __restrict__ g_out)
{
    __shared__ Smem sm;

    const int b    = blockIdx.z;
    const int y    = blockIdx.y;
    const int dyg  = blockIdx.x;          // 0..2
    const int tid  = threadIdx.x;
    const int w    = tid >> 5;            // warp = local dy
    const int lane = tid & 31;
    const int p    = lane >> 4;           // parity
    const int g    = lane & 15;
    const int U    = g << 2;              // base deint index (multiple of 4)
    const int dy0  = dyg * NW;

    // Zero the x-pad regions (u in [0,10) and [74,84)) once; interior is
    // rewritten every chunk, OOB-row handling zero-fills via predicate.
    for (int e = tid; e < NW * CK * 2 * 20; e += NTHREADS) {
        int u = e % 20; u = (u < 10) ? u : (u + 64);
        int rest = e / 20;
        int pp = rest & 1;
        int cc = (rest >> 1) & (CK - 1);
        int ww = rest >> 3;
        sm.in2s[ww][cc][pp][u] = 0.0f;
    }

    const size_t plane  = (size_t)H * W;
    const size_t cstep  = (size_t)CK * plane;   // pointer advance per chunk

    float acc[4][21];
    #pragma unroll
    for (int i = 0; i < 4; ++i)
        #pragma unroll
        for (int j = 0; j < 21; ++j) acc[i][j] = 0.0f;

    // ---- loop-invariant loader state ----
    // in2: 896 float4 per chunk; e4 = q*224 + tid
    const float* gp2[4];
    float*       sp2[4];    // smem deint store base (even-parity float2 slot)
    bool         l_ok[4];
    #pragma unroll
    for (int q = 0; q < 4; ++q) {
        int e4   = q * NTHREADS + tid;
        int col4 = e4 & 31;
        int cc   = (e4 >> 5) & 3;
        int ww   = e4 >> 7;                 // 0..6
        int row2 = y + 2 * (dy0 + ww) - 20; // [-20, 115]
        l_ok[q]  = (row2 >= 0) && (row2 < H);
        gp2[q]   = g_in2 + ((size_t)b * C_TOT + cc) * plane + row2 * W + col4 * 4;
        sp2[q]   = &sm.in2s[ww][cc][0][2 * col4 + 10];   // odd parity = +84
    }
    // in1: 128 float4 per chunk; only tid<128 loads
    const bool   i1_act = (tid < 128);
    const float* gp1 = g_in1 + ((size_t)b * C_TOT + (tid >> 5 & 3)) * plane
                             + (size_t)y * W + (tid & 31) * 4;
    float*       sp1 = &sm.in1s[tid >> 5 & 3][0][2 * (tid & 31)];  // odd = +64

    float4 pf2[4], pf1;

    // prefetch chunk 0
    #pragma unroll
    for (int q = 0; q < 4; ++q)
        pf2[q] = l_ok[q] ? *(const float4*)gp2[q] : make_float4(0.f, 0.f, 0.f, 0.f);
    if (i1_act) pf1 = *(const float4*)gp1;

    for (int k = 0; k < NCHUNK; ++k) {
        __syncthreads();  // previous chunk fully consumed

        // store prefetched chunk, de-interleaving by parity:
        // float4 = cols 4c..4c+3 -> even pair {x,z}, odd pair {y,w}
        #pragma unroll
        for (int q = 0; q < 4; ++q) {
            *(float2*)(sp2[q])      = make_float2(pf2[q].x, pf2[q].z);
            *(float2*)(sp2[q] + 84) = make_float2(pf2[q].y, pf2[q].w);
        }
        if (i1_act) {
            *(float2*)(sp1)      = make_float2(pf1.x, pf1.z);
            *(float2*)(sp1 + 64) = make_float2(pf1.y, pf1.w);
        }
        __syncthreads();  // smem ready

        // prefetch chunk k+1 (latency hidden under compute below)
        if (k + 1 < NCHUNK) {
            #pragma unroll
            for (int q = 0; q < 4; ++q) {
                gp2[q] += cstep;
                pf2[q] = l_ok[q] ? *(const float4*)gp2[q]
                                 : make_float4(0.f, 0.f, 0.f, 0.f);
            }
            gp1 += cstep;
            if (i1_act) pf1 = *(const float4*)gp1;
        }

        // ---- compute chunk k: per channel 7x LDS.128 -> 84 FFMA ----
        #pragma unroll
        for (int cc = 0; cc < CK; ++cc) {
            float4 av = *(const float4*)&sm.in1s[cc][p][U];
            float a0 = av.x, a1 = av.y, a2 = av.z, a3 = av.w;
            float r[24];
            #pragma unroll
            for (int q = 0; q < 6; ++q)
                *(float4*)&r[4 * q] = *(const float4*)&sm.in2s[w][cc][p][U + 4 * q];
            #pragma unroll
            for (int j = 0; j < 21; ++j) {
                acc[0][j] = fmaf(a0, r[j + 0], acc[0][j]);
                acc[1][j] = fmaf(a1, r[j + 1], acc[1][j]);
                acc[2][j] = fmaf(a2, r[j + 2], acc[2][j]);
                acc[3][j] = fmaf(a3, r[j + 3], acc[3][j]);
            }
        }
    }

    // ---- epilogue: smem transpose -> fully coalesced 512B row stores ----
    const float scale = 1.0f / 256.0f;
    const int   dy    = dy0 + w;
    float* outb = g_out + (((size_t)b * (DD * DD)) * H + y) * W;
    #pragma unroll
    for (int j = 0; j < 21; ++j) {
        #pragma unroll
        for (int i = 0; i < 4; ++i)
            sm.stage[w][2 * (U + i) + p] = acc[i][j] * scale;
        __syncwarp();
        float4 v = *(const float4*)&sm.stage[w][lane * 4];
        *(float4*)(outb + (size_t)(dy * DD + j) * plane + lane * 4) = v;
        __syncwarp();
    }
}

extern "C" void kernel_launch(void* const* d_in, const int* in_sizes, int n_in,
                              void* d_out, int out_size)
{
    (void)in_sizes; (void)n_in; (void)out_size;
    const float* in1 = (const float*)d_in[0];
    const float* in2 = (const float*)d_in[1];
    float*       out = (float*)d_out;

    dim3 grid(3, H, 8);      // (dy-group, y, b) -> 2304 blocks
    dim3 block(NTHREADS);    // 224 = 7 warps
    corr_kernel<<<grid, block>>>(in1, in2, out);
}